// round 4
// baseline (speedup 1.0000x reference)
#include <cuda_runtime.h>
#include <cuda_bf16.h>

// Problem constants
#define BB   32
#define CC   512
#define NN   1024          // H*W = 32*32
#define CQ   64
#define MR   640           // Cq + Cq + C  (rows of concatenated weight)

// ---------------- scratch (no cudaMalloc allowed) ----------------
__device__ float g_scale[3];                     // 1/sigma for q,k,v
__device__ float g_wcat[MR * CC];                // scaled concatenated weights [640][512]
__device__ float g_bcat[MR];                     // concatenated bias
__device__ float g_qkv[BB * MR * NN];            // per batch: rows 0..63 q, 64..127 k, 128..639 v  (all [chan][n])
__device__ float g_p[(size_t)BB * NN * NN];      // exp(qk)  [b][n_query][m_key]
__device__ float g_cinv[BB * NN];                // 1 / colsum

// =================================================================
// Spectral norm: sigma = || W * normalize(W^T u) ||   (forward value)
// one block per weight, 512 threads
// =================================================================
__global__ void spectral_k(const float* __restrict__ Wq, const float* __restrict__ uq,
                           const float* __restrict__ Wk, const float* __restrict__ uk,
                           const float* __restrict__ Wv, const float* __restrict__ uv) {
    const float* W; const float* u; int out;
    if (blockIdx.x == 0)      { W = Wq; u = uq; out = CQ; }
    else if (blockIdx.x == 1) { W = Wk; u = uk; out = CQ; }
    else                      { W = Wv; u = uv; out = CC; }
    const int in = CC;

    __shared__ float sv[CC];
    __shared__ float st[CC];
    __shared__ float red[16];

    int tid  = threadIdx.x;           // 512 threads
    int lane = tid & 31, w = tid >> 5;

    // v[j] = sum_i W[i][j] * u[i]   (coalesced: thread j reads column j)
    float acc = 0.f;
    for (int i = 0; i < out; i++) acc += W[i * in + tid] * u[i];
    sv[tid] = acc;

    // ||v||
    float s = acc * acc;
    #pragma unroll
    for (int o = 16; o; o >>= 1) s += __shfl_xor_sync(0xffffffffu, s, o);
    if (lane == 0) red[w] = s;
    __syncthreads();
    if (tid < 16) {
        float r = red[tid];
        #pragma unroll
        for (int o = 8; o; o >>= 1) r += __shfl_xor_sync(0xffffu, r, o);
        if (tid == 0) red[0] = r;
    }
    __syncthreads();
    float inv = rsqrtf(red[0]);       // 1/||v||
    __syncthreads();                  // everyone has read red[0]

    // t[i] = (W v)[i], one warp per row group (coalesced within warp)
    for (int i = w; i < out; i += 16) {
        float a = 0.f;
        for (int j = lane; j < in; j += 32) a += W[i * in + j] * sv[j];
        #pragma unroll
        for (int o = 16; o; o >>= 1) a += __shfl_xor_sync(0xffffffffu, a, o);
        if (lane == 0) st[i] = a * inv;
    }
    __syncthreads();

    // sigma^2 = sum t^2
    float q = (tid < out) ? st[tid] * st[tid] : 0.f;
    #pragma unroll
    for (int o = 16; o; o >>= 1) q += __shfl_xor_sync(0xffffffffu, q, o);
    if (lane == 0) red[w] = q;
    __syncthreads();
    if (tid == 0) {
        float r = 0.f;
        #pragma unroll
        for (int i = 0; i < 16; i++) r += red[i];
        g_scale[blockIdx.x] = rsqrtf(r);      // 1/sigma
    }
}

// =================================================================
// Build scaled concatenated weight [640][512] and bias [640]
// =================================================================
__global__ void build_wcat(const float* __restrict__ Wq, const float* __restrict__ bq,
                           const float* __restrict__ Wk, const float* __restrict__ bk,
                           const float* __restrict__ Wv, const float* __restrict__ bv) {
    int idx = blockIdx.x * blockDim.x + threadIdx.x;    // 640*512
    if (idx >= MR * CC) return;
    int r = idx >> 9, c = idx & (CC - 1);
    float wv, sc;
    if (r < CQ)            { wv = Wq[r * CC + c];          sc = g_scale[0]; }
    else if (r < 2 * CQ)   { wv = Wk[(r - CQ) * CC + c];   sc = g_scale[1]; }
    else                   { wv = Wv[(r - 2*CQ) * CC + c]; sc = g_scale[2]; }
    g_wcat[idx] = wv * sc;
    if (c == 0)
        g_bcat[r] = (r < CQ) ? bq[r] : (r < 2*CQ ? bk[r - CQ] : bv[r - 2*CQ]);
}

// =================================================================
// GEMM 1: qkv[b][r][n] = wcat[r][:] . x[b][:][n] + bcat[r]
// A row-major [M=640][K=512], B row-major [K=512][N=1024]
// 128x128 tile, BK=8, 256 threads, 8x8/thread (stride-16 interleave)
// =================================================================
__global__ __launch_bounds__(256, 2)
void gemm_proj(const float* __restrict__ x) {
    int b  = blockIdx.z;
    int m0 = blockIdx.y * 128;
    int n0 = blockIdx.x * 128;
    const float* A  = g_wcat;
    const float* Bm = x + (size_t)b * CC * NN;

    __shared__ float As[8][132];   // padded: transposed store conflict-free
    __shared__ float Bs[8][128];

    float acc[8][8];
    #pragma unroll
    for (int i = 0; i < 8; i++)
        #pragma unroll
        for (int j = 0; j < 8; j++) acc[i][j] = 0.f;

    int tid = threadIdx.x;
    int tx = tid & 15, ty = tid >> 4;
    int a_m = tid >> 3, a_k = tid & 7;     // A tile: 32 rows/pass x 4
    int b_k = tid >> 5, b_n = tid & 31;    // B tile: 8 rows, 32 cols/pass x 4

    float ra[4], rb[4];
    #pragma unroll
    for (int i = 0; i < 4; i++) ra[i] = A[(m0 + a_m + 32*i) * CC + a_k];
    #pragma unroll
    for (int i = 0; i < 4; i++) rb[i] = Bm[b_k * NN + n0 + b_n + 32*i];

    const int KT = CC / 8;
    for (int kt = 0; kt < KT; kt++) {
        __syncthreads();
        #pragma unroll
        for (int i = 0; i < 4; i++) As[a_k][a_m + 32*i] = ra[i];
        #pragma unroll
        for (int i = 0; i < 4; i++) Bs[b_k][b_n + 32*i] = rb[i];
        __syncthreads();
        if (kt + 1 < KT) {
            int k0 = (kt + 1) * 8;
            #pragma unroll
            for (int i = 0; i < 4; i++) ra[i] = A[(m0 + a_m + 32*i) * CC + k0 + a_k];
            #pragma unroll
            for (int i = 0; i < 4; i++) rb[i] = Bm[(k0 + b_k) * NN + n0 + b_n + 32*i];
        }
        #pragma unroll
        for (int kk = 0; kk < 8; kk++) {
            float af[8], bf[8];
            #pragma unroll
            for (int i = 0; i < 8; i++) af[i] = As[kk][ty + 16*i];
            #pragma unroll
            for (int j = 0; j < 8; j++) bf[j] = Bs[kk][tx + 16*j];
            #pragma unroll
            for (int i = 0; i < 8; i++)
                #pragma unroll
                for (int j = 0; j < 8; j++) acc[i][j] += af[i] * bf[j];
        }
    }

    float* Cp = g_qkv + (size_t)b * MR * NN;
    #pragma unroll
    for (int i = 0; i < 8; i++) {
        int r = m0 + ty + 16*i;
        float bias = g_bcat[r];
        #pragma unroll
        for (int j = 0; j < 8; j++)
            Cp[r * NN + n0 + tx + 16*j] = acc[i][j] + bias;
    }
}

// =================================================================
// GEMM 2: p[b][n][m] = exp( sum_o q[b][o][n] * k[b][o][m] )
// Both operands are [K=64][1024] channel-major -> direct (no transpose) loads
// =================================================================
__global__ __launch_bounds__(256, 2)
void gemm_qk(void) {
    int b  = blockIdx.z;
    int m0 = blockIdx.y * 128;   // query-n block
    int n0 = blockIdx.x * 128;   // key-m block
    const float* Aq = g_qkv + (size_t)b * MR * NN;            // q: rows 0..63
    const float* Bk = g_qkv + (size_t)b * MR * NN + CQ * NN;  // k: rows 64..127

    __shared__ float As[8][128];
    __shared__ float Bs[8][128];

    float acc[8][8];
    #pragma unroll
    for (int i = 0; i < 8; i++)
        #pragma unroll
        for (int j = 0; j < 8; j++) acc[i][j] = 0.f;

    int tid = threadIdx.x;
    int tx = tid & 15, ty = tid >> 4;
    int l_k = tid >> 5, l_c = tid & 31;

    float ra[4], rb[4];
    #pragma unroll
    for (int i = 0; i < 4; i++) ra[i] = Aq[l_k * NN + m0 + l_c + 32*i];
    #pragma unroll
    for (int i = 0; i < 4; i++) rb[i] = Bk[l_k * NN + n0 + l_c + 32*i];

    const int KT = CQ / 8;    // 8
    for (int kt = 0; kt < KT; kt++) {
        __syncthreads();
        #pragma unroll
        for (int i = 0; i < 4; i++) As[l_k][l_c + 32*i] = ra[i];
        #pragma unroll
        for (int i = 0; i < 4; i++) Bs[l_k][l_c + 32*i] = rb[i];
        __syncthreads();
        if (kt + 1 < KT) {
            int k0 = (kt + 1) * 8;
            #pragma unroll
            for (int i = 0; i < 4; i++) ra[i] = Aq[(k0 + l_k) * NN + m0 + l_c + 32*i];
            #pragma unroll
            for (int i = 0; i < 4; i++) rb[i] = Bk[(k0 + l_k) * NN + n0 + l_c + 32*i];
        }
        #pragma unroll
        for (int kk = 0; kk < 8; kk++) {
            float af[8], bf[8];
            #pragma unroll
            for (int i = 0; i < 8; i++) af[i] = As[kk][ty + 16*i];
            #pragma unroll
            for (int j = 0; j < 8; j++) bf[j] = Bs[kk][tx + 16*j];
            #pragma unroll
            for (int i = 0; i < 8; i++)
                #pragma unroll
                for (int j = 0; j < 8; j++) acc[i][j] += af[i] * bf[j];
        }
    }

    float* Pp = g_p + (size_t)b * NN * NN;
    #pragma unroll
    for (int i = 0; i < 8; i++) {
        int nq = m0 + ty + 16*i;
        #pragma unroll
        for (int j = 0; j < 8; j++)
            Pp[(size_t)nq * NN + n0 + tx + 16*j] = __expf(acc[i][j]);
    }
}

// =================================================================
// Column sums (over query axis n) -> inverse
// grid (32 batches, 32 m-chunks), 256 threads: 8 n-slices x 32 cols
// =================================================================
__global__ void colsum_k(void) {
    int b  = blockIdx.x;
    int m0 = blockIdx.y * 32;
    int ml = threadIdx.x & 31;
    int ns = threadIdx.x >> 5;   // 0..7
    const float* p = g_p + (size_t)b * NN * NN + m0;
    float s0 = 0.f, s1 = 0.f;
    for (int n = ns; n < NN; n += 16) {
        s0 += p[(size_t)n * NN + ml];
        s1 += p[(size_t)(n + 8) * NN + ml];
    }
    __shared__ float part[8][32];
    part[ns][ml] = s0 + s1;
    __syncthreads();
    if (threadIdx.x < 32) {
        float t = 0.f;
        #pragma unroll
        for (int i = 0; i < 8; i++) t += part[i][threadIdx.x];
        g_cinv[b * NN + m0 + threadIdx.x] = 1.0f / t;
    }
}

// =================================================================
// GEMM 3: out[b][c][m] = gamma * (sum_n v[b][c][n] p[b][n][m]) * cinv[b][m] + x[b][c][m]
// A = v row-major [512][1024], B = p [1024][1024]
// =================================================================
__global__ __launch_bounds__(256, 2)
void gemm_av(const float* __restrict__ x, const float* __restrict__ gamma,
             float* __restrict__ out) {
    int b  = blockIdx.z;
    int m0 = blockIdx.y * 128;   // channel block
    int n0 = blockIdx.x * 128;   // spatial block
    const float* A  = g_qkv + (size_t)b * MR * NN + 2 * CQ * NN;  // v rows
    const float* Bm = g_p + (size_t)b * NN * NN;

    __shared__ float As[8][132];
    __shared__ float Bs[8][128];

    float acc[8][8];
    #pragma unroll
    for (int i = 0; i < 8; i++)
        #pragma unroll
        for (int j = 0; j < 8; j++) acc[i][j] = 0.f;

    int tid = threadIdx.x;
    int tx = tid & 15, ty = tid >> 4;
    int a_m = tid >> 3, a_k = tid & 7;
    int b_k = tid >> 5, b_n = tid & 31;

    float ra[4], rb[4];
    #pragma unroll
    for (int i = 0; i < 4; i++) ra[i] = A[(m0 + a_m + 32*i) * NN + a_k];
    #pragma unroll
    for (int i = 0; i < 4; i++) rb[i] = Bm[(size_t)b_k * NN + n0 + b_n + 32*i];

    const int KT = NN / 8;   // 128
    for (int kt = 0; kt < KT; kt++) {
        __syncthreads();
        #pragma unroll
        for (int i = 0; i < 4; i++) As[a_k][a_m + 32*i] = ra[i];
        #pragma unroll
        for (int i = 0; i < 4; i++) Bs[b_k][b_n + 32*i] = rb[i];
        __syncthreads();
        if (kt + 1 < KT) {
            int k0 = (kt + 1) * 8;
            #pragma unroll
            for (int i = 0; i < 4; i++) ra[i] = A[(m0 + a_m + 32*i) * NN + k0 + a_k];
            #pragma unroll
            for (int i = 0; i < 4; i++) rb[i] = Bm[(size_t)(k0 + b_k) * NN + n0 + b_n + 32*i];
        }
        #pragma unroll
        for (int kk = 0; kk < 8; kk++) {
            float af[8], bf[8];
            #pragma unroll
            for (int i = 0; i < 8; i++) af[i] = As[kk][ty + 16*i];
            #pragma unroll
            for (int j = 0; j < 8; j++) bf[j] = Bs[kk][tx + 16*j];
            #pragma unroll
            for (int i = 0; i < 8; i++)
                #pragma unroll
                for (int j = 0; j < 8; j++) acc[i][j] += af[i] * bf[j];
        }
    }

    float gm = *gamma;
    float scl[8];
    #pragma unroll
    for (int j = 0; j < 8; j++) scl[j] = gm * g_cinv[b * NN + n0 + tx + 16*j];

    #pragma unroll
    for (int i = 0; i < 8; i++) {
        int c = m0 + ty + 16*i;
        size_t rowo = (size_t)b * CC * NN + (size_t)c * NN;
        #pragma unroll
        for (int j = 0; j < 8; j++) {
            size_t o = rowo + n0 + tx + 16*j;
            out[o] = scl[j] * acc[i][j] + x[o];
        }
    }
}

// =================================================================
extern "C" void kernel_launch(void* const* d_in, const int* in_sizes, int n_in,
                              void* d_out, int out_size) {
    const float* x     = (const float*)d_in[0];
    const float* Wq    = (const float*)d_in[1];
    const float* bq    = (const float*)d_in[2];
    const float* uq    = (const float*)d_in[3];
    const float* Wk    = (const float*)d_in[4];
    const float* bk    = (const float*)d_in[5];
    const float* uk    = (const float*)d_in[6];
    const float* Wv    = (const float*)d_in[7];
    const float* bv    = (const float*)d_in[8];
    const float* uv    = (const float*)d_in[9];
    const float* gamma = (const float*)d_in[10];
    float* out = (float*)d_out;

    spectral_k<<<3, 512>>>(Wq, uq, Wk, uk, Wv, uv);
    build_wcat<<<(MR * CC + 255) / 256, 256>>>(Wq, bq, Wk, bk, Wv, bv);
    gemm_proj<<<dim3(NN/128, MR/128, BB), 256>>>(x);
    gemm_qk<<<dim3(NN/128, NN/128, BB), 256>>>();
    colsum_k<<<dim3(BB, NN/32), 256>>>();
    gemm_av<<<dim3(NN/128, CC/128, BB), 256>>>(x, gamma, out);
}